// round 5
// baseline (speedup 1.0000x reference)
#include <cuda_runtime.h>
#include <math.h>
#include <float.h>

// Problem dims
#define Bn   8
#define N1D  256
#define N2D  256
#define FD   128
#define ROWS (Bn * N1D)          // 2048
#define KD   128

// Phase-1 GEMM tiling: 64x64 tile per 256-thread CTA, 4x4 microtile.
#define RT  64
#define CT  64
#define LDT 68                   // padded minor dim of [k][c] smem tiles
#define LDA32 36                 // padded minor dim for 32-row A tiles

// ---------------- device scratch (no allocations allowed) ----------------
__device__ float g_Mx2[Bn * N2D * FD];       // M(x2)            [2048,128]
__device__ float g_m1 [ROWS * FD];           // W(x1)            [2048,128]
__device__ float g_gh [ROWS * 3 * FD];       // x1 @ whh^T + bhh [2048,384]
__device__ float g_x  [ROWS * FD];           // relu(m1+m2)      [2048,128]
__device__ float g_gi [ROWS * 3 * FD];       // x @ wih^T + bih  [2048,384]
__device__ int   g_cnt [ROWS];               // valid-edge counts
__device__ int   g_list[ROWS * N2D];         // valid-edge j lists

// ---------------- 64x64 SGEMM tile (phase 1) ------------------------------
__device__ __forceinline__ void gemm_tile(
    const float* __restrict__ A, const float* __restrict__ W,
    const float* __restrict__ b,
    float* __restrict__ C, int ldC, int rowbase, int colbase, float* sm)
{
    float* As = sm;                   // [KD][LDT]
    float* Ws = sm + KD * LDT;        // [KD][LDT]
    const int tid  = threadIdx.x;
    const int lane = tid & 31, warp = tid >> 5;
    const int kq = lane & 3;
    const int rr = lane >> 2;
    const int r  = warp * 8 + rr;     // 0..63

#pragma unroll
    for (int it = 0; it < 8; it++) {
        int kk = it * 4 + kq;
        float4 av = *(const float4*)(A + (size_t)(rowbase + r) * KD + kk * 4);
        As[(kk * 4 + 0) * LDT + r] = av.x;
        As[(kk * 4 + 1) * LDT + r] = av.y;
        As[(kk * 4 + 2) * LDT + r] = av.z;
        As[(kk * 4 + 3) * LDT + r] = av.w;
        float4 wv = *(const float4*)(W + (size_t)(colbase + r) * KD + kk * 4);
        Ws[(kk * 4 + 0) * LDT + r] = wv.x;
        Ws[(kk * 4 + 1) * LDT + r] = wv.y;
        Ws[(kk * 4 + 2) * LDT + r] = wv.z;
        Ws[(kk * 4 + 3) * LDT + r] = wv.w;
    }
    __syncthreads();

    const int cg = tid & 15;
    const int rg = tid >> 4;

    float acc[4][4];
#pragma unroll
    for (int i = 0; i < 4; i++)
#pragma unroll
        for (int j = 0; j < 4; j++) acc[i][j] = 0.0f;

    const float* ap = As + rg * 4;
    const float* wp = Ws + cg * 4;

#pragma unroll 8
    for (int k = 0; k < KD; k++) {
        float4 a = *(const float4*)(ap + k * LDT);
        float4 w = *(const float4*)(wp + k * LDT);
        acc[0][0] += a.x * w.x; acc[0][1] += a.x * w.y; acc[0][2] += a.x * w.z; acc[0][3] += a.x * w.w;
        acc[1][0] += a.y * w.x; acc[1][1] += a.y * w.y; acc[1][2] += a.y * w.z; acc[1][3] += a.y * w.w;
        acc[2][0] += a.z * w.x; acc[2][1] += a.z * w.y; acc[2][2] += a.z * w.z; acc[2][3] += a.z * w.w;
        acc[3][0] += a.w * w.x; acc[3][1] += a.w * w.y; acc[3][2] += a.w * w.z; acc[3][3] += a.w * w.w;
    }

    float4 bv = *(const float4*)(b + colbase + cg * 4);
#pragma unroll
    for (int i = 0; i < 4; i++) {
        float4 o;
        o.x = acc[i][0] + bv.x;
        o.y = acc[i][1] + bv.y;
        o.z = acc[i][2] + bv.z;
        o.w = acc[i][3] + bv.w;
        *(float4*)(C + (size_t)(rowbase + rg * 4 + i) * ldC + colbase + cg * 4) = o;
    }
}

// Edge-list compaction for 8 rows (one warp per row).
__device__ __forceinline__ void lists_block(const float* __restrict__ ve, int rowblock)
{
    int w = threadIdx.x >> 5, lane = threadIdx.x & 31;
    int row = rowblock * 8 + w;
    const float* mrow = ve + (size_t)row * N2D;
    int base = 0;
#pragma unroll
    for (int r = 0; r < 8; r++) {
        int j = r * 32 + lane;
        float v = mrow[j];
        unsigned bal = __ballot_sync(0xffffffffu, v != 0.0f);
        if (v != 0.0f)
            g_list[(size_t)row * N2D + base + __popc(bal & ((1u << lane) - 1u))] = j;
        base += __popc(bal);
    }
    if (lane == 0) g_cnt[row] = base;
}

// Phase 1 (576 blocks): [0,64) Mx2, [64,128) m1, [128,320) gh, [320,576) lists
__global__ void __launch_bounds__(256, 3) k_p1(
    const float* __restrict__ x1, const float* __restrict__ x2,
    const float* __restrict__ ve,
    const float* __restrict__ W_w, const float* __restrict__ W_b,
    const float* __restrict__ M_w, const float* __restrict__ M_b,
    const float* __restrict__ whh, const float* __restrict__ bhh)
{
    extern __shared__ float sm[];
    int bid = blockIdx.x;
    if (bid < 64) {
        gemm_tile(x2, M_w, M_b, g_Mx2, FD, (bid & 31) * RT, (bid >> 5) * CT, sm);
    } else if (bid < 128) {
        int t = bid - 64;
        gemm_tile(x1, W_w, W_b, g_m1, FD, (t & 31) * RT, (t >> 5) * CT, sm);
    } else if (bid < 320) {
        int t = bid - 128;
        gemm_tile(x1, whh, bhh, g_gh, 3 * FD, (t & 31) * RT, (t >> 5) * CT, sm);
    } else {
        lists_block(ve, bid - 320);
    }
}

// ---------------- gi GEMM: 32x64 tiles, 2x4 microtile, 4 CTAs/SM ----------
__global__ void __launch_bounds__(256, 4) k_gemmGI(
    const float* __restrict__ wih, const float* __restrict__ bih)
{
    extern __shared__ float sm[];
    float* As = sm;                   // [KD][LDA32]  (32 rows)
    float* Ws = sm + KD * LDA32;      // [KD][LDT]    (64 cols)
    const int tid = threadIdx.x;
    const int rowbase = blockIdx.x * 32;
    const int colbase = blockIdx.y * CT;

    // Stage A tile (32x128): 1024 float4, 4 per thread, transposed.
#pragma unroll
    for (int it = 0; it < 4; it++) {
        int idx = tid + it * 256;
        int r = idx >> 5, kk = idx & 31;
        float4 av = *(const float4*)(g_x + (size_t)(rowbase + r) * KD + kk * 4);
        As[(kk * 4 + 0) * LDA32 + r] = av.x;
        As[(kk * 4 + 1) * LDA32 + r] = av.y;
        As[(kk * 4 + 2) * LDA32 + r] = av.z;
        As[(kk * 4 + 3) * LDA32 + r] = av.w;
    }
    // Stage W tile (64x128): 2048 float4, 8 per thread, transposed.
#pragma unroll
    for (int it = 0; it < 8; it++) {
        int idx = tid + it * 256;
        int c = idx >> 5, kk = idx & 31;
        float4 wv = *(const float4*)(wih + (size_t)(colbase + c) * KD + kk * 4);
        Ws[(kk * 4 + 0) * LDT + c] = wv.x;
        Ws[(kk * 4 + 1) * LDT + c] = wv.y;
        Ws[(kk * 4 + 2) * LDT + c] = wv.z;
        Ws[(kk * 4 + 3) * LDT + c] = wv.w;
    }
    __syncthreads();

    const int cg = tid & 15;          // 16 col groups x 4 cols
    const int rg = tid >> 4;          // 16 row groups x 2 rows

    float acc[2][4];
#pragma unroll
    for (int i = 0; i < 2; i++)
#pragma unroll
        for (int j = 0; j < 4; j++) acc[i][j] = 0.0f;

    const float* ap = As + rg * 2;
    const float* wp = Ws + cg * 4;

#pragma unroll 8
    for (int k = 0; k < KD; k++) {
        float2 a = *(const float2*)(ap + k * LDA32);
        float4 w = *(const float4*)(wp + k * LDT);
        acc[0][0] += a.x * w.x; acc[0][1] += a.x * w.y; acc[0][2] += a.x * w.z; acc[0][3] += a.x * w.w;
        acc[1][0] += a.y * w.x; acc[1][1] += a.y * w.y; acc[1][2] += a.y * w.z; acc[1][3] += a.y * w.w;
    }

    float4 bv = *(const float4*)(bih + colbase + cg * 4);
#pragma unroll
    for (int i = 0; i < 2; i++) {
        float4 o;
        o.x = acc[i][0] + bv.x;
        o.y = acc[i][1] + bv.y;
        o.z = acc[i][2] + bv.z;
        o.w = acc[i][3] + bv.w;
        *(float4*)(g_gi + (size_t)(rowbase + rg * 2 + i) * 3 * FD + colbase + cg * 4) = o;
    }
}

// ---------------- sparse masked max + relu(m1 + m2) -----------------------
__device__ __forceinline__ float4 max4(float4 a, float4 b) {
    float4 r;
    r.x = fmaxf(a.x, b.x); r.y = fmaxf(a.y, b.y);
    r.z = fmaxf(a.z, b.z); r.w = fmaxf(a.w, b.w);
    return r;
}

__global__ void __launch_bounds__(256) k_maskmax()
{
    int warp = threadIdx.x >> 5, lane = threadIdx.x & 31;
    int row = blockIdx.x * 8 + warp;
    int b = row >> 8;
    const float4* __restrict__ Mb = (const float4*)(g_Mx2 + (size_t)b * N2D * FD);
    const int* __restrict__ lst = g_list + (size_t)row * N2D;
    int cnt = g_cnt[row];

    float4 m = make_float4(-FLT_MAX, -FLT_MAX, -FLT_MAX, -FLT_MAX);
    int t = 0;
    for (; t + 4 <= cnt; t += 4) {
        int j0 = __ldg(lst + t),     j1 = __ldg(lst + t + 1);
        int j2 = __ldg(lst + t + 2), j3 = __ldg(lst + t + 3);
        float4 v0 = Mb[j0 * 32 + lane];
        float4 v1 = Mb[j1 * 32 + lane];
        float4 v2 = Mb[j2 * 32 + lane];
        float4 v3 = Mb[j3 * 32 + lane];
        m = max4(m, max4(max4(v0, v1), max4(v2, v3)));
    }
    for (; t < cnt; t++)
        m = max4(m, Mb[__ldg(lst + t) * 32 + lane]);
    if (cnt < N2D) {
        float4 z = make_float4(0.f, 0.f, 0.f, 0.f);
        m = max4(m, z);
    }
    float4 m1v = ((const float4*)g_m1)[row * 32 + lane];
    float4 x;
    x.x = fmaxf(m1v.x + m.x, 0.f);
    x.y = fmaxf(m1v.y + m.y, 0.f);
    x.z = fmaxf(m1v.z + m.z, 0.f);
    x.w = fmaxf(m1v.w + m.w, 0.f);
    ((float4*)g_x)[row * 32 + lane] = x;
}

// ---------------- GRU gates (fast approx, float4) --------------------------
__device__ __forceinline__ float sigf(float t) {
    return __fdividef(1.0f, 1.0f + __expf(-t));
}
__device__ __forceinline__ float tanh_approx(float t) {
    float y;
    asm("tanh.approx.f32 %0, %1;" : "=f"(y) : "f"(t));
    return y;
}

__global__ void __launch_bounds__(256) k_gates(
    const float* __restrict__ x1, float* __restrict__ out)
{
    int idx = blockIdx.x * 256 + threadIdx.x;   // one float4 (4 feats)
    int row = idx >> 5, fq = idx & 31;          // fq: which float4 of 32
    const float4* gi = (const float4*)(g_gi + (size_t)row * 384);
    const float4* gh = (const float4*)(g_gh + (size_t)row * 384);
    float4 ir = gi[fq],      hr = gh[fq];
    float4 iz = gi[32 + fq], hz = gh[32 + fq];
    float4 in_ = gi[64 + fq], hn = gh[64 + fq];
    float4 hp = ((const float4*)x1)[idx];
    float4 o;
    {
        float r = sigf(ir.x + hr.x), z = sigf(iz.x + hz.x);
        float n = tanh_approx(in_.x + r * hn.x);
        o.x = (1.0f - z) * n + z * hp.x;
    }
    {
        float r = sigf(ir.y + hr.y), z = sigf(iz.y + hz.y);
        float n = tanh_approx(in_.y + r * hn.y);
        o.y = (1.0f - z) * n + z * hp.y;
    }
    {
        float r = sigf(ir.z + hr.z), z = sigf(iz.z + hz.z);
        float n = tanh_approx(in_.z + r * hn.z);
        o.z = (1.0f - z) * n + z * hp.z;
    }
    {
        float r = sigf(ir.w + hr.w), z = sigf(iz.w + hz.w);
        float n = tanh_approx(in_.w + r * hn.w);
        o.w = (1.0f - z) * n + z * hp.w;
    }
    ((float4*)out)[idx] = o;
}

// ---------------- launch ---------------------------------------------------
extern "C" void kernel_launch(void* const* d_in, const int* in_sizes, int n_in,
                              void* d_out, int out_size)
{
    const float* x1  = (const float*)d_in[0];
    const float* x2  = (const float*)d_in[1];
    const float* ve  = (const float*)d_in[2];
    const float* W_w = (const float*)d_in[3];
    const float* W_b = (const float*)d_in[4];
    const float* M_w = (const float*)d_in[5];
    const float* M_b = (const float*)d_in[6];
    const float* wih = (const float*)d_in[7];
    const float* whh = (const float*)d_in[8];
    const float* bih = (const float*)d_in[9];
    const float* bhh = (const float*)d_in[10];
    float* out = (float*)d_out;

    const int smemP1 = 2 * KD * LDT * (int)sizeof(float);            // 69632
    const int smemGI = KD * (LDA32 + LDT) * (int)sizeof(float);      // 53248
    cudaFuncSetAttribute(k_p1,     cudaFuncAttributeMaxDynamicSharedMemorySize, smemP1);
    cudaFuncSetAttribute(k_gemmGI, cudaFuncAttributeMaxDynamicSharedMemorySize, smemGI);

    k_p1<<<576, 256, smemP1>>>(x1, x2, ve, W_w, W_b, M_w, M_b, whh, bhh);
    k_maskmax<<<ROWS / 8, 256>>>();
    k_gemmGI<<<dim3(ROWS / 32, 6), 256, smemGI>>>(wih, bih);
    k_gates<<<(ROWS * FD / 4) / 256, 256>>>(x1, out);
}

// round 7
// speedup vs baseline: 1.2620x; 1.2620x over previous
#include <cuda_runtime.h>
#include <math.h>
#include <float.h>

// Problem dims
#define Bn   8
#define N1D  256
#define N2D  256
#define FD   128
#define ROWS (Bn * N1D)          // 2048
#define KD   128

// GEMM tiling: 64x64 tile per 256-thread CTA, 4x4 microtile.
#define RT  64
#define CT  64
#define LDT 68                   // padded minor dim of [k][*] smem tiles

// ---------------- device scratch (no allocations allowed) ----------------
__device__ float g_Mx2[Bn * N2D * FD];       // M(x2)            [2048,128]
__device__ float g_m1 [ROWS * FD];           // W(x1)            [2048,128]
__device__ float g_gh [ROWS * 3 * FD];       // x1 @ whh^T + bhh [2048,384]
__device__ float g_x  [ROWS * FD];           // relu(m1+m2)      [2048,128]
__device__ float g_gi [ROWS * 3 * FD];       // x @ wih^T + bih  [2048,384]
__device__ int   g_cnt [ROWS];               // valid-edge counts
__device__ int   g_list[ROWS * N2D];         // valid-edge j lists

// ---------------- 64x64 SGEMM tile ----------------------------------------
// Smem tiles K-major ([k][r]/[k][c]); staging lane->row mapping is
// conflict-free; inner loop: 2x LDS.128 + 16 FFMA.
__device__ __forceinline__ void gemm_tile(
    const float* __restrict__ A, const float* __restrict__ W,
    const float* __restrict__ b,
    float* __restrict__ C, int ldC, int rowbase, int colbase, float* sm)
{
    float* As = sm;                   // [KD][LDT]
    float* Ws = sm + KD * LDT;        // [KD][LDT]
    const int tid  = threadIdx.x;
    const int lane = tid & 31, warp = tid >> 5;
    const int kq = lane & 3;
    const int rr = lane >> 2;
    const int r  = warp * 8 + rr;     // 0..63

#pragma unroll
    for (int it = 0; it < 8; it++) {
        int kk = it * 4 + kq;
        float4 av = *(const float4*)(A + (size_t)(rowbase + r) * KD + kk * 4);
        As[(kk * 4 + 0) * LDT + r] = av.x;
        As[(kk * 4 + 1) * LDT + r] = av.y;
        As[(kk * 4 + 2) * LDT + r] = av.z;
        As[(kk * 4 + 3) * LDT + r] = av.w;
        float4 wv = *(const float4*)(W + (size_t)(colbase + r) * KD + kk * 4);
        Ws[(kk * 4 + 0) * LDT + r] = wv.x;
        Ws[(kk * 4 + 1) * LDT + r] = wv.y;
        Ws[(kk * 4 + 2) * LDT + r] = wv.z;
        Ws[(kk * 4 + 3) * LDT + r] = wv.w;
    }
    __syncthreads();

    const int cg = tid & 15;
    const int rg = tid >> 4;

    float acc[4][4];
#pragma unroll
    for (int i = 0; i < 4; i++)
#pragma unroll
        for (int j = 0; j < 4; j++) acc[i][j] = 0.0f;

    const float* ap = As + rg * 4;
    const float* wp = Ws + cg * 4;

#pragma unroll 8
    for (int k = 0; k < KD; k++) {
        float4 a = *(const float4*)(ap + k * LDT);
        float4 w = *(const float4*)(wp + k * LDT);
        acc[0][0] += a.x * w.x; acc[0][1] += a.x * w.y; acc[0][2] += a.x * w.z; acc[0][3] += a.x * w.w;
        acc[1][0] += a.y * w.x; acc[1][1] += a.y * w.y; acc[1][2] += a.y * w.z; acc[1][3] += a.y * w.w;
        acc[2][0] += a.z * w.x; acc[2][1] += a.z * w.y; acc[2][2] += a.z * w.z; acc[2][3] += a.z * w.w;
        acc[3][0] += a.w * w.x; acc[3][1] += a.w * w.y; acc[3][2] += a.w * w.z; acc[3][3] += a.w * w.w;
    }

    float4 bv = *(const float4*)(b + colbase + cg * 4);
#pragma unroll
    for (int i = 0; i < 4; i++) {
        float4 o;
        o.x = acc[i][0] + bv.x;
        o.y = acc[i][1] + bv.y;
        o.z = acc[i][2] + bv.z;
        o.w = acc[i][3] + bv.w;
        *(float4*)(C + (size_t)(rowbase + rg * 4 + i) * ldC + colbase + cg * 4) = o;
    }
}

// Edge-list compaction for 8 rows (one warp per row).
__device__ __forceinline__ void lists_block(const float* __restrict__ ve, int rowblock)
{
    int w = threadIdx.x >> 5, lane = threadIdx.x & 31;
    int row = rowblock * 8 + w;
    const float* mrow = ve + (size_t)row * N2D;
    int base = 0;
#pragma unroll
    for (int r = 0; r < 8; r++) {
        int j = r * 32 + lane;
        float v = mrow[j];
        unsigned bal = __ballot_sync(0xffffffffu, v != 0.0f);
        if (v != 0.0f)
            g_list[(size_t)row * N2D + base + __popc(bal & ((1u << lane) - 1u))] = j;
        base += __popc(bal);
    }
    if (lane == 0) g_cnt[row] = base;
}

// Phase 1 (576 blocks): [0,64) Mx2, [64,128) m1, [128,320) gh, [320,576) lists
__global__ void __launch_bounds__(256, 3) k_p1(
    const float* __restrict__ x1, const float* __restrict__ x2,
    const float* __restrict__ ve,
    const float* __restrict__ W_w, const float* __restrict__ W_b,
    const float* __restrict__ M_w, const float* __restrict__ M_b,
    const float* __restrict__ whh, const float* __restrict__ bhh)
{
    extern __shared__ float sm[];
    int bid = blockIdx.x;
    if (bid < 64) {
        gemm_tile(x2, M_w, M_b, g_Mx2, FD, (bid & 31) * RT, (bid >> 5) * CT, sm);
    } else if (bid < 128) {
        int t = bid - 64;
        gemm_tile(x1, W_w, W_b, g_m1, FD, (t & 31) * RT, (t >> 5) * CT, sm);
    } else if (bid < 320) {
        int t = bid - 128;
        gemm_tile(x1, whh, bhh, g_gh, 3 * FD, (t & 31) * RT, (t >> 5) * CT, sm);
    } else {
        lists_block(ve, bid - 320);
    }
}

// gi = x @ wih^T + bih  (64x64 tiles, occ 3 — proven R4 config)
__global__ void __launch_bounds__(256, 3) k_gemmGI(
    const float* __restrict__ wih, const float* __restrict__ bih)
{
    extern __shared__ float sm[];
    gemm_tile(g_x, wih, bih, g_gi, 3 * FD, blockIdx.x * RT, blockIdx.y * CT, sm);
}

// ---------------- sparse masked max + relu(m1 + m2) -----------------------
__device__ __forceinline__ float4 max4(float4 a, float4 b) {
    float4 r;
    r.x = fmaxf(a.x, b.x); r.y = fmaxf(a.y, b.y);
    r.z = fmaxf(a.z, b.z); r.w = fmaxf(a.w, b.w);
    return r;
}

__global__ void __launch_bounds__(256) k_maskmax()
{
    int warp = threadIdx.x >> 5, lane = threadIdx.x & 31;
    int row = blockIdx.x * 8 + warp;
    int b = row >> 8;
    const float4* __restrict__ Mb = (const float4*)(g_Mx2 + (size_t)b * N2D * FD);
    const int* __restrict__ lst = g_list + (size_t)row * N2D;
    int cnt = g_cnt[row];

    float4 m = make_float4(-FLT_MAX, -FLT_MAX, -FLT_MAX, -FLT_MAX);
    int t = 0;
    for (; t + 4 <= cnt; t += 4) {
        int j0 = __ldg(lst + t),     j1 = __ldg(lst + t + 1);
        int j2 = __ldg(lst + t + 2), j3 = __ldg(lst + t + 3);
        float4 v0 = Mb[j0 * 32 + lane];
        float4 v1 = Mb[j1 * 32 + lane];
        float4 v2 = Mb[j2 * 32 + lane];
        float4 v3 = Mb[j3 * 32 + lane];
        m = max4(m, max4(max4(v0, v1), max4(v2, v3)));
    }
    for (; t < cnt; t++)
        m = max4(m, Mb[__ldg(lst + t) * 32 + lane]);
    if (cnt < N2D) {
        float4 z = make_float4(0.f, 0.f, 0.f, 0.f);
        m = max4(m, z);
    }
    float4 m1v = ((const float4*)g_m1)[row * 32 + lane];
    float4 x;
    x.x = fmaxf(m1v.x + m.x, 0.f);
    x.y = fmaxf(m1v.y + m.y, 0.f);
    x.z = fmaxf(m1v.z + m.z, 0.f);
    x.w = fmaxf(m1v.w + m.w, 0.f);
    ((float4*)g_x)[row * 32 + lane] = x;
}

// ---------------- GRU gates (fast approx, float4, 128-thr blocks) ----------
__device__ __forceinline__ float sigf(float t) {
    return __fdividef(1.0f, 1.0f + __expf(-t));
}
__device__ __forceinline__ float tanh_approx(float t) {
    float y;
    asm("tanh.approx.f32 %0, %1;" : "=f"(y) : "f"(t));
    return y;
}

__global__ void __launch_bounds__(128) k_gates(
    const float* __restrict__ x1, float* __restrict__ out)
{
    int idx = blockIdx.x * 128 + threadIdx.x;   // one float4 (4 feats)
    int row = idx >> 5, fq = idx & 31;
    const float4* gi = (const float4*)(g_gi + (size_t)row * 384);
    const float4* gh = (const float4*)(g_gh + (size_t)row * 384);
    // Batch all 7 independent loads up front (MLP=7).
    float4 ir = __ldg(gi + fq);
    float4 iz = __ldg(gi + 32 + fq);
    float4 in_ = __ldg(gi + 64 + fq);
    float4 hr = __ldg(gh + fq);
    float4 hz = __ldg(gh + 32 + fq);
    float4 hn = __ldg(gh + 64 + fq);
    float4 hp = __ldg((const float4*)x1 + idx);
    float4 o;
    {
        float r = sigf(ir.x + hr.x), z = sigf(iz.x + hz.x);
        float n = tanh_approx(in_.x + r * hn.x);
        o.x = (1.0f - z) * n + z * hp.x;
    }
    {
        float r = sigf(ir.y + hr.y), z = sigf(iz.y + hz.y);
        float n = tanh_approx(in_.y + r * hn.y);
        o.y = (1.0f - z) * n + z * hp.y;
    }
    {
        float r = sigf(ir.z + hr.z), z = sigf(iz.z + hz.z);
        float n = tanh_approx(in_.z + r * hn.z);
        o.z = (1.0f - z) * n + z * hp.z;
    }
    {
        float r = sigf(ir.w + hr.w), z = sigf(iz.w + hz.w);
        float n = tanh_approx(in_.w + r * hn.w);
        o.w = (1.0f - z) * n + z * hp.w;
    }
    ((float4*)out)[idx] = o;
}

// ---------------- launch ---------------------------------------------------
extern "C" void kernel_launch(void* const* d_in, const int* in_sizes, int n_in,
                              void* d_out, int out_size)
{
    const float* x1  = (const float*)d_in[0];
    const float* x2  = (const float*)d_in[1];
    const float* ve  = (const float*)d_in[2];
    const float* W_w = (const float*)d_in[3];
    const float* W_b = (const float*)d_in[4];
    const float* M_w = (const float*)d_in[5];
    const float* M_b = (const float*)d_in[6];
    const float* wih = (const float*)d_in[7];
    const float* whh = (const float*)d_in[8];
    const float* bih = (const float*)d_in[9];
    const float* bhh = (const float*)d_in[10];
    float* out = (float*)d_out;

    const int smem = 2 * KD * LDT * (int)sizeof(float);   // 69632 B
    cudaFuncSetAttribute(k_p1,     cudaFuncAttributeMaxDynamicSharedMemorySize, smem);
    cudaFuncSetAttribute(k_gemmGI, cudaFuncAttributeMaxDynamicSharedMemorySize, smem);

    k_p1<<<576, 256, smem>>>(x1, x2, ve, W_w, W_b, M_w, M_b, whh, bhh);
    k_maskmax<<<ROWS / 8, 256>>>();
    k_gemmGI<<<dim3(ROWS / RT, 6), 256, smem>>>(wih, bih);
    k_gates<<<(ROWS * FD / 4) / 128, 128>>>(x1, out);
}